// round 1
// baseline (speedup 1.0000x reference)
#include <cuda_runtime.h>
#include <cstdint>
#include <math.h>

// Problem constants
#define ROWS_TOTAL 16384          // B*T = 32*512
#define DDIM 2048                 // feature dim
#define KC 128                    // K per chunk
#define NCHUNK (DDIM / KC)        // 16
#define C4_PER_CHUNK (KC / 4)     // 32 float4 columns per chunk
#define TILE_ROWS 64
#define NCTA (ROWS_TOTAL / TILE_ROWS)   // 256
#define NTHREADS 256

#define SF_STRIDE 65                              // float4 stride for sF (pad: conflict-free)
#define SF_BYTES (C4_PER_CHUNK * SF_STRIDE * 16)  // 33280
#define SW_BYTES (C4_PER_CHUNK * 16 * 16)         // 8192  (32 c4 x 16 j x float4)
#define STAGE_BYTES (SF_BYTES + SW_BYTES)         // 41472
#define SMEM_BYTES (2 * STAGE_BYTES)              // 82944

#define BOXES_ELEMS (ROWS_TOTAL * 12)             // 196608
#define CONF_ELEMS  (ROWS_TOTAL * 3)              // 49152

// Packed weights: [c4 (512)][j (16)][kk (4)] floats; j=0..11 bbox, 12..14 conf, 15 pad=0
__device__ __align__(16) float g_wpack[512 * 16 * 4];

__device__ __forceinline__ uint32_t smem_u32(const void* p) {
    uint32_t a;
    asm("{ .reg .u64 t; cvta.to.shared.u64 t, %1; cvt.u32.u64 %0, t; }" : "=r"(a) : "l"(p));
    return a;
}
__device__ __forceinline__ void cp_async16(uint32_t dst, const void* src) {
    asm volatile("cp.async.cg.shared.global [%0], [%1], 16;\n" :: "r"(dst), "l"(src) : "memory");
}

__global__ void prepack_kernel(const float* __restrict__ Wb, const float* __restrict__ Wc) {
    int idx = blockIdx.x * blockDim.x + threadIdx.x;   // 0 .. 32767
    if (idx < 512 * 64) {
        int c4 = idx >> 6;
        int j  = (idx >> 2) & 15;
        int kk = idx & 3;
        int k = c4 * 4 + kk;
        float v = 0.0f;
        if (j < 12)      v = Wb[k * 12 + j];
        else if (j < 15) v = Wc[k * 3 + (j - 12)];
        g_wpack[idx] = v;
    }
}

extern __shared__ char smem[];

__global__ void __launch_bounds__(NTHREADS, 1)
detector_main(const float* __restrict__ feat,
              const float* __restrict__ bb,     // b_bbox[12]
              const float* __restrict__ bc,     // b_conf[3]
              float* __restrict__ out,
              int writeConf, int writeValid)
{
    const int t = threadIdx.x;
    const int rowBase = blockIdx.x * TILE_ROWS;
    const int s  = t >> 4;     // k-slice 0..15
    const int rg = t & 15;     // row group 0..15 (owns rows rg, rg+16, rg+32, rg+48)
    const uint32_t smemBase = smem_u32(smem);

    // ---- async stage loader: features (k-packed float4, swizzled) + packed weights ----
    auto load_stage = [&](int chunk, int buf) {
        const int k0 = chunk * KC;
        const uint32_t base = smemBase + (uint32_t)buf * STAGE_BYTES;
        // features: 64 rows x 32 float4 = 2048 cp.async of 16B
        #pragma unroll
        for (int i = 0; i < 8; ++i) {
            int e = i * 256 + t;
            int row = e >> 5;          // 0..63
            int c4  = e & 31;          // 0..31
            const float4* src = reinterpret_cast<const float4*>(
                feat + (size_t)(rowBase + row) * DDIM + k0) + c4;
            uint32_t dst = base + (uint32_t)(c4 * SF_STRIDE + row) * 16u;
            cp_async16(dst, src);
        }
        // weights: 512 float4 (contiguous slice of g_wpack)
        const float4* wsrc = reinterpret_cast<const float4*>(g_wpack) + (size_t)(k0 / 4) * 16;
        const uint32_t wb = base + SF_BYTES;
        #pragma unroll
        for (int i = 0; i < 2; ++i) {
            int e = i * 256 + t;
            cp_async16(wb + (uint32_t)e * 16u, wsrc + e);
        }
        asm volatile("cp.async.commit_group;\n" ::: "memory");
    };

    // ---- accumulators: 4 rows x 16 j, packed f32x2 over K-pairs ----
    unsigned long long acc[4][16];
    #pragma unroll
    for (int d = 0; d < 4; ++d)
        #pragma unroll
        for (int j = 0; j < 16; ++j)
            acc[d][j] = 0ull;

    load_stage(0, 0);

    #pragma unroll 1
    for (int ch = 0; ch < NCHUNK; ++ch) {
        if (ch + 1 < NCHUNK) {
            load_stage(ch + 1, (ch + 1) & 1);
            asm volatile("cp.async.wait_group 1;\n" ::: "memory");
        } else {
            asm volatile("cp.async.wait_group 0;\n" ::: "memory");
        }
        __syncthreads();

        const uint32_t base = smemBase + (uint32_t)(ch & 1) * STAGE_BYTES;
        #pragma unroll
        for (int cc = 0; cc < 2; ++cc) {
            const int c4 = s + 16 * cc;
            // features for 4 rows (rg + 16d), 4 k each, as 2x b64 (k-pairs)
            unsigned long long fa[4][2];
            const uint32_t fb = base + (uint32_t)(c4 * SF_STRIDE + rg) * 16u;
            #pragma unroll
            for (int d = 0; d < 4; ++d) {
                asm ("ld.shared.v2.u64 {%0,%1},[%2];"
                     : "=l"(fa[d][0]), "=l"(fa[d][1]) : "r"(fb + (uint32_t)(d * 256)));
            }
            const uint32_t wa = base + SF_BYTES + (uint32_t)c4 * 256u;
            #pragma unroll
            for (int j = 0; j < 16; ++j) {
                unsigned long long w01, w23;
                asm ("ld.shared.v2.u64 {%0,%1},[%2];"
                     : "=l"(w01), "=l"(w23) : "r"(wa + (uint32_t)(j * 16)));
                #pragma unroll
                for (int d = 0; d < 4; ++d) {
                    asm ("fma.rn.f32x2 %0,%1,%2,%0;" : "+l"(acc[d][j]) : "l"(fa[d][0]), "l"(w01));
                    asm ("fma.rn.f32x2 %0,%1,%2,%0;" : "+l"(acc[d][j]) : "l"(fa[d][1]), "l"(w23));
                }
            }
        }
        __syncthreads();
    }

    // ---- reduce: collapse f32x2 halves, then across 16 k-slices ----
    float val[4][16];
    #pragma unroll
    for (int d = 0; d < 4; ++d)
        #pragma unroll
        for (int j = 0; j < 16; ++j) {
            uint32_t lo, hi;
            asm ("mov.b64 {%0,%1},%2;" : "=r"(lo), "=r"(hi) : "l"(acc[d][j]));
            val[d][j] = __uint_as_float(lo) + __uint_as_float(hi);
        }
    // slices s and s^1 are lanes l and l^16 of the same warp
    #pragma unroll
    for (int d = 0; d < 4; ++d)
        #pragma unroll
        for (int j = 0; j < 16; ++j)
            val[d][j] += __shfl_xor_sync(0xffffffffu, val[d][j], 16);

    float* sRed = reinterpret_cast<float*>(smem);              // [8 warps][64 rows][16 j] = 32KB
    const int w = t >> 5;
    if ((t & 31) < 16) {
        #pragma unroll
        for (int d = 0; d < 4; ++d)
            #pragma unroll
            for (int j = 0; j < 16; ++j)
                sRed[(w * 64 + (rg + 16 * d)) * 16 + j] = val[d][j];
    }
    __syncthreads();

    float* sOut = reinterpret_cast<float*>(smem + 8 * 64 * 16 * 4);  // [64][17]
    #pragma unroll
    for (int i = 0; i < 4; ++i) {
        int o = t + 256 * i;          // 0..1023
        int row = o >> 4, j = o & 15;
        float sum = 0.0f;
        #pragma unroll
        for (int ww = 0; ww < 8; ++ww) sum += sRed[(ww * 64 + row) * 16 + j];
        sOut[row * 17 + j] = sum;
    }
    __syncthreads();

    // ---- epilogue: bias + sigmoid + stable top-3 + threshold + stores ----
    if (t < TILE_ROWS) {
        float v[16];
        #pragma unroll
        for (int j = 0; j < 16; ++j) v[j] = sOut[t * 17 + j];

        float bx[12];
        #pragma unroll
        for (int j = 0; j < 12; ++j) bx[j] = v[j] + bb[j];
        float conf[3];
        #pragma unroll
        for (int a = 0; a < 3; ++a)
            conf[a] = 1.0f / (1.0f + expf(-(v[12 + a] + bc[a])));

        // stable descending sort of 3 (matches jax.lax.top_k tie-breaking)
        int i0 = 0, i1 = 1, i2 = 2, tmp;
        if (conf[i0] < conf[i1]) { tmp = i0; i0 = i1; i1 = tmp; }
        if (conf[i1] < conf[i2]) { tmp = i1; i1 = i2; i2 = tmp; }
        if (conf[i0] < conf[i1]) { tmp = i0; i0 = i1; i1 = tmp; }
        int ord[3] = { i0, i1, i2 };

        const int grow = rowBase + t;
        float4* bo = reinterpret_cast<float4*>(out);   // boxes: [row][3][4]
        #pragma unroll
        for (int slot = 0; slot < 3; ++slot) {
            int a = ord[slot];
            float c = conf[a];
            bool vld = c > 0.5f;
            float4 b4 = vld ? make_float4(bx[a * 4 + 0], bx[a * 4 + 1], bx[a * 4 + 2], bx[a * 4 + 3])
                            : make_float4(0.f, 0.f, 0.f, 0.f);
            bo[grow * 3 + slot] = b4;
            if (writeConf)  out[BOXES_ELEMS + grow * 3 + slot] = c;
            if (writeValid) out[BOXES_ELEMS + CONF_ELEMS + grow * 3 + slot] = vld ? 1.0f : 0.0f;
        }
    }
}

extern "C" void kernel_launch(void* const* d_in, const int* in_sizes, int n_in,
                              void* d_out, int out_size) {
    const float* feat = (const float*)d_in[0];   // [32,512,2048] f32
    const float* Wb   = (const float*)d_in[1];   // [2048,12]
    const float* bb   = (const float*)d_in[2];   // [12]
    const float* Wc   = (const float*)d_in[3];   // [2048,3]
    const float* bc   = (const float*)d_in[4];   // [3]
    float* out = (float*)d_out;

    cudaFuncSetAttribute(detector_main, cudaFuncAttributeMaxDynamicSharedMemorySize, SMEM_BYTES);

    prepack_kernel<<<64, 512>>>(Wb, Wc);

    int writeConf  = (out_size >= BOXES_ELEMS + CONF_ELEMS) ? 1 : 0;
    int writeValid = (out_size >= BOXES_ELEMS + 2 * CONF_ELEMS) ? 1 : 0;
    detector_main<<<NCTA, NTHREADS, SMEM_BYTES>>>(feat, bb, bc, out, writeConf, writeValid);
}

// round 2
// speedup vs baseline: 1.4581x; 1.4581x over previous
#include <cuda_runtime.h>
#include <cstdint>
#include <math.h>

// Problem constants
#define ROWS_TOTAL 16384          // B*T = 32*512
#define DDIM 2048                 // feature dim
#define KC 128                    // K per chunk
#define NCHUNK (DDIM / KC)        // 16
#define C4_PER_CHUNK (KC / 4)     // 32 float4 columns per chunk
#define TILE_ROWS 32
#define NCTA (ROWS_TOTAL / TILE_ROWS)   // 512
#define NTHREADS 256

#define SF_STRIDE 33                               // float4 stride per row (pad: conflict-free)
#define SF_BYTES (TILE_ROWS * SF_STRIDE * 16)      // 16896
#define SW_BYTES (C4_PER_CHUNK * 16 * 16)          // 8192  (32 c4 x 16 j x float4)
#define STAGE_BYTES (SF_BYTES + SW_BYTES)          // 25088
#define NBUF 3
#define SMEM_BYTES (NBUF * STAGE_BYTES)            // 75264

#define BOXES_ELEMS (ROWS_TOTAL * 12)              // 196608
#define CONF_ELEMS  (ROWS_TOTAL * 3)               // 49152

// Packed weights: [c4 (512)][j (16)][kk (4)] floats; j=0..11 bbox, 12..14 conf, 15 pad=0
__device__ __align__(16) float g_wpack[512 * 16 * 4];

__device__ __forceinline__ uint32_t smem_u32(const void* p) {
    uint32_t a;
    asm("{ .reg .u64 t; cvta.to.shared.u64 t, %1; cvt.u32.u64 %0, t; }" : "=r"(a) : "l"(p));
    return a;
}
__device__ __forceinline__ void cp_async16(uint32_t dst, const void* src) {
    asm volatile("cp.async.cg.shared.global [%0], [%1], 16;\n" :: "r"(dst), "l"(src) : "memory");
}

__global__ void prepack_kernel(const float* __restrict__ Wb, const float* __restrict__ Wc) {
    int idx = blockIdx.x * blockDim.x + threadIdx.x;   // 0 .. 32767
    if (idx < 512 * 64) {
        int c4 = idx >> 6;
        int j  = (idx >> 2) & 15;
        int kk = idx & 3;
        int k = c4 * 4 + kk;
        float v = 0.0f;
        if (j < 12)      v = Wb[k * 12 + j];
        else if (j < 15) v = Wc[k * 3 + (j - 12)];
        g_wpack[idx] = v;
    }
}

extern __shared__ char smem[];

__global__ void __launch_bounds__(NTHREADS, 2)
detector_main(const float* __restrict__ feat,
              const float* __restrict__ bb,     // b_bbox[12]
              const float* __restrict__ bc,     // b_conf[3]
              float* __restrict__ out,
              int writeConf, int writeValid)
{
    const int t = threadIdx.x;
    const int rowBase = blockIdx.x * TILE_ROWS;
    const int s  = t >> 4;     // k-slice 0..15
    const int rg = t & 15;     // row group (owns rows rg, rg+16)
    const uint32_t smemBase = smem_u32(smem);

    // ---- async stage loader: features ([row][c4] float4, stride 33) + packed weights ----
    auto load_stage = [&](int chunk, int buf) {
        const int k0 = chunk * KC;
        const uint32_t base = smemBase + (uint32_t)buf * STAGE_BYTES;
        // features: 32 rows x 32 float4 = 1024 cp.async of 16B (stores coalesced per warp)
        #pragma unroll
        for (int i = 0; i < 4; ++i) {
            int e = i * 256 + t;
            int row = e >> 5;          // 0..31
            int c4  = e & 31;          // 0..31
            const float4* src = reinterpret_cast<const float4*>(
                feat + (size_t)(rowBase + row) * DDIM + k0) + c4;
            uint32_t dst = base + (uint32_t)(row * SF_STRIDE + c4) * 16u;
            cp_async16(dst, src);
        }
        // weights: 512 float4 (contiguous slice of g_wpack)
        const float4* wsrc = reinterpret_cast<const float4*>(g_wpack) + (size_t)chunk * 512;
        const uint32_t wb = base + SF_BYTES;
        #pragma unroll
        for (int i = 0; i < 2; ++i) {
            int e = i * 256 + t;
            cp_async16(wb + (uint32_t)e * 16u, wsrc + e);
        }
        asm volatile("cp.async.commit_group;\n" ::: "memory");
    };

    // ---- accumulators: 2 rows x 16 j, packed f32x2 over K-pairs ----
    unsigned long long acc[2][16];
    #pragma unroll
    for (int d = 0; d < 2; ++d)
        #pragma unroll
        for (int j = 0; j < 16; ++j)
            acc[d][j] = 0ull;

    load_stage(0, 0);
    load_stage(1, 1);

    #pragma unroll 1
    for (int ch = 0; ch < NCHUNK; ++ch) {
        if (ch < NCHUNK - 1) {
            asm volatile("cp.async.wait_group 1;\n" ::: "memory");
        } else {
            asm volatile("cp.async.wait_group 0;\n" ::: "memory");
        }
        __syncthreads();

        const uint32_t base = smemBase + (uint32_t)(ch % NBUF) * STAGE_BYTES;
        #pragma unroll
        for (int cc = 0; cc < 2; ++cc) {
            const int c4 = s + 16 * cc;
            // features for rows rg, rg+16: one LDS.128 each (4 k)
            unsigned long long fa[2][2];
            #pragma unroll
            for (int d = 0; d < 2; ++d) {
                uint32_t fb = base + (uint32_t)((rg + 16 * d) * SF_STRIDE + c4) * 16u;
                asm ("ld.shared.v2.u64 {%0,%1},[%2];"
                     : "=l"(fa[d][0]), "=l"(fa[d][1]) : "r"(fb));
            }
            const uint32_t wa = base + SF_BYTES + (uint32_t)c4 * 256u;
            #pragma unroll
            for (int j = 0; j < 16; ++j) {
                unsigned long long w01, w23;
                asm ("ld.shared.v2.u64 {%0,%1},[%2];"
                     : "=l"(w01), "=l"(w23) : "r"(wa + (uint32_t)(j * 16)));
                #pragma unroll
                for (int d = 0; d < 2; ++d) {
                    asm ("fma.rn.f32x2 %0,%1,%2,%0;" : "+l"(acc[d][j]) : "l"(fa[d][0]), "l"(w01));
                    asm ("fma.rn.f32x2 %0,%1,%2,%0;" : "+l"(acc[d][j]) : "l"(fa[d][1]), "l"(w23));
                }
            }
        }

        if (ch + 2 < NCHUNK) {
            load_stage(ch + 2, (ch + 2) % NBUF);
        }
    }
    __syncthreads();   // all warps done reading stage buffers before reuse as sRed

    // ---- reduce: collapse f32x2 halves, then across 16 k-slices ----
    float val[2][16];
    #pragma unroll
    for (int d = 0; d < 2; ++d)
        #pragma unroll
        for (int j = 0; j < 16; ++j) {
            uint32_t lo, hi;
            asm ("mov.b64 {%0,%1},%2;" : "=r"(lo), "=r"(hi) : "l"(acc[d][j]));
            val[d][j] = __uint_as_float(lo) + __uint_as_float(hi);
        }
    // lanes l and l^16 share rg, adjacent s
    #pragma unroll
    for (int d = 0; d < 2; ++d)
        #pragma unroll
        for (int j = 0; j < 16; ++j)
            val[d][j] += __shfl_xor_sync(0xffffffffu, val[d][j], 16);

    float* sRed = reinterpret_cast<float*>(smem);          // [8 warps][32 rows][17] pad
    const int w = t >> 5;
    if ((t & 31) < 16) {
        #pragma unroll
        for (int d = 0; d < 2; ++d)
            #pragma unroll
            for (int j = 0; j < 16; ++j)
                sRed[(w * TILE_ROWS + (rg + 16 * d)) * 17 + j] = val[d][j];
    }
    __syncthreads();

    float* sOut = reinterpret_cast<float*>(smem + 8 * TILE_ROWS * 17 * 4);  // [32][17]
    {
        int o = t;                       // 0..255 covers 0..511 in 2 steps
        #pragma unroll
        for (int i = 0; i < 2; ++i, o += 256) {
            int row = o >> 4, j = o & 15;
            float sum = 0.0f;
            #pragma unroll
            for (int ww = 0; ww < 8; ++ww) sum += sRed[(ww * TILE_ROWS + row) * 17 + j];
            sOut[row * 17 + j] = sum;
        }
    }
    __syncthreads();

    // ---- epilogue: bias + sigmoid + stable top-3 + threshold + stores ----
    if (t < TILE_ROWS) {
        float v[16];
        #pragma unroll
        for (int j = 0; j < 16; ++j) v[j] = sOut[t * 17 + j];

        float bx[12];
        #pragma unroll
        for (int j = 0; j < 12; ++j) bx[j] = v[j] + bb[j];
        float conf[3];
        #pragma unroll
        for (int a = 0; a < 3; ++a)
            conf[a] = 1.0f / (1.0f + expf(-(v[12 + a] + bc[a])));

        // stable descending sort of 3 (matches jax.lax.top_k tie-breaking)
        int i0 = 0, i1 = 1, i2 = 2, tmp;
        if (conf[i0] < conf[i1]) { tmp = i0; i0 = i1; i1 = tmp; }
        if (conf[i1] < conf[i2]) { tmp = i1; i1 = i2; i2 = tmp; }
        if (conf[i0] < conf[i1]) { tmp = i0; i0 = i1; i1 = tmp; }
        int ord[3] = { i0, i1, i2 };

        const int grow = rowBase + t;
        float4* bo = reinterpret_cast<float4*>(out);   // boxes: [row][3][4]
        #pragma unroll
        for (int slot = 0; slot < 3; ++slot) {
            int a = ord[slot];
            float c = conf[a];
            bool vld = c > 0.5f;
            float4 b4 = vld ? make_float4(bx[a * 4 + 0], bx[a * 4 + 1], bx[a * 4 + 2], bx[a * 4 + 3])
                            : make_float4(0.f, 0.f, 0.f, 0.f);
            bo[grow * 3 + slot] = b4;
            if (writeConf)  out[BOXES_ELEMS + grow * 3 + slot] = c;
            if (writeValid) out[BOXES_ELEMS + CONF_ELEMS + grow * 3 + slot] = vld ? 1.0f : 0.0f;
        }
    }
}

extern "C" void kernel_launch(void* const* d_in, const int* in_sizes, int n_in,
                              void* d_out, int out_size) {
    const float* feat = (const float*)d_in[0];   // [32,512,2048] f32
    const float* Wb   = (const float*)d_in[1];   // [2048,12]
    const float* bb   = (const float*)d_in[2];   // [12]
    const float* Wc   = (const float*)d_in[3];   // [2048,3]
    const float* bc   = (const float*)d_in[4];   // [3]
    float* out = (float*)d_out;

    cudaFuncSetAttribute(detector_main, cudaFuncAttributeMaxDynamicSharedMemorySize, SMEM_BYTES);

    prepack_kernel<<<64, 512>>>(Wb, Wc);

    int writeConf  = (out_size >= BOXES_ELEMS + CONF_ELEMS) ? 1 : 0;
    int writeValid = (out_size >= BOXES_ELEMS + 2 * CONF_ELEMS) ? 1 : 0;
    detector_main<<<NCTA, NTHREADS, SMEM_BYTES>>>(feat, bb, bc, out, writeConf, writeValid);
}

// round 3
// speedup vs baseline: 1.4723x; 1.0098x over previous
#include <cuda_runtime.h>
#include <cstdint>
#include <math.h>

// Problem constants
#define ROWS_TOTAL 16384          // B*T = 32*512
#define DDIM 2048                 // feature dim
#define KC 128                    // K per chunk
#define NCHUNK (DDIM / KC)        // 16
#define C4_PER_CHUNK (KC / 4)     // 32 float4 columns per chunk
#define TILE_ROWS 32
#define NCTA (ROWS_TOTAL / TILE_ROWS)   // 512
#define NTHREADS 256

#define SF_STRIDE 33                               // float4 stride per row (pad: conflict-free)
#define SF_BYTES (TILE_ROWS * SF_STRIDE * 16)      // 16896
#define SW_BYTES (C4_PER_CHUNK * 16 * 16)          // 8192  (32 c4 x 16 j x float4)
#define STAGE_BYTES (SF_BYTES + SW_BYTES)          // 25088
#define NBUF 3
#define SMEM_BYTES (NBUF * STAGE_BYTES)            // 75264

#define BOXES_ELEMS (ROWS_TOTAL * 12)              // 196608
#define CONF_ELEMS  (ROWS_TOTAL * 3)               // 49152

// Packed weights: [c4 (512)][j (16)][kk (4)] floats; j=0..11 bbox, 12..14 conf, 15 pad=0
__device__ __align__(16) float g_wpack[512 * 16 * 4];

__device__ __forceinline__ uint32_t smem_u32(const void* p) {
    uint32_t a;
    asm("{ .reg .u64 t; cvta.to.shared.u64 t, %1; cvt.u32.u64 %0, t; }" : "=r"(a) : "l"(p));
    return a;
}
__device__ __forceinline__ void cp_async16(uint32_t dst, const void* src) {
    asm volatile("cp.async.cg.shared.global [%0], [%1], 16;\n" :: "r"(dst), "l"(src) : "memory");
}

__global__ void prepack_kernel(const float* __restrict__ Wb, const float* __restrict__ Wc) {
    int idx = blockIdx.x * blockDim.x + threadIdx.x;   // 0 .. 32767
    if (idx < 512 * 64) {
        int c4 = idx >> 6;
        int j  = (idx >> 2) & 15;
        int kk = idx & 3;
        int k = c4 * 4 + kk;
        float v = 0.0f;
        if (j < 12)      v = Wb[k * 12 + j];
        else if (j < 15) v = Wc[k * 3 + (j - 12)];
        g_wpack[idx] = v;
    }
}

extern __shared__ char smem[];

__global__ void __launch_bounds__(NTHREADS, 3)
detector_main(const float* __restrict__ feat,
              const float* __restrict__ bb,     // b_bbox[12]
              const float* __restrict__ bc,     // b_conf[3]
              float* __restrict__ out,
              int writeConf, int writeValid)
{
    const int t = threadIdx.x;
    const int rowBase = blockIdx.x * TILE_ROWS;
    const int s  = t >> 5;            // k-slice / warp id 0..7 (covers c4 = s + 8*cc)
    const int jh = (t >> 4) & 1;      // j-half: j0 = jh*8
    const int rg = t & 15;            // row group (owns rows rg, rg+16)
    const int j0 = jh * 8;
    const uint32_t smemBase = smem_u32(smem);

    // ---- async stage loader: features ([row][c4] float4, stride 33) + packed weights ----
    auto load_stage = [&](int chunk, int buf) {
        const int k0 = chunk * KC;
        const uint32_t base = smemBase + (uint32_t)buf * STAGE_BYTES;
        // features: 32 rows x 32 float4 = 1024 cp.async of 16B (stores coalesced per warp)
        #pragma unroll
        for (int i = 0; i < 4; ++i) {
            int e = i * 256 + t;
            int row = e >> 5;          // 0..31
            int c4  = e & 31;          // 0..31
            const float4* src = reinterpret_cast<const float4*>(
                feat + (size_t)(rowBase + row) * DDIM + k0) + c4;
            uint32_t dst = base + (uint32_t)(row * SF_STRIDE + c4) * 16u;
            cp_async16(dst, src);
        }
        // weights: 512 float4 (contiguous slice of g_wpack)
        const float4* wsrc = reinterpret_cast<const float4*>(g_wpack) + (size_t)chunk * 512;
        const uint32_t wb = base + SF_BYTES;
        #pragma unroll
        for (int i = 0; i < 2; ++i) {
            int e = i * 256 + t;
            cp_async16(wb + (uint32_t)e * 16u, wsrc + e);
        }
        asm volatile("cp.async.commit_group;\n" ::: "memory");
    };

    // ---- accumulators: 2 rows x 8 j, packed f32x2 over K-pairs ----
    unsigned long long acc[2][8];
    #pragma unroll
    for (int d = 0; d < 2; ++d)
        #pragma unroll
        for (int j = 0; j < 8; ++j)
            acc[d][j] = 0ull;

    load_stage(0, 0);
    load_stage(1, 1);

    #pragma unroll 1
    for (int ch = 0; ch < NCHUNK; ++ch) {
        if (ch < NCHUNK - 1) {
            asm volatile("cp.async.wait_group 1;\n" ::: "memory");
        } else {
            asm volatile("cp.async.wait_group 0;\n" ::: "memory");
        }
        __syncthreads();

        // Prefetch ch+2 NOW: buffer (ch+2)%3 == (ch-1)%3, fully consumed before this barrier.
        if (ch + 2 < NCHUNK) {
            load_stage(ch + 2, (ch + 2) % NBUF);
        }

        const uint32_t base = smemBase + (uint32_t)(ch % NBUF) * STAGE_BYTES;
        #pragma unroll
        for (int cc = 0; cc < 4; ++cc) {
            const int c4 = s + 8 * cc;
            // features for rows rg, rg+16: one LDS.128 each (4 k)
            unsigned long long fa[2][2];
            #pragma unroll
            for (int d = 0; d < 2; ++d) {
                uint32_t fb = base + (uint32_t)((rg + 16 * d) * SF_STRIDE + c4) * 16u;
                asm ("ld.shared.v2.u64 {%0,%1},[%2];"
                     : "=l"(fa[d][0]), "=l"(fa[d][1]) : "r"(fb));
            }
            const uint32_t wa = base + SF_BYTES + (uint32_t)(c4 * 16 + j0) * 16u;
            #pragma unroll
            for (int j = 0; j < 8; ++j) {
                unsigned long long w01, w23;
                asm ("ld.shared.v2.u64 {%0,%1},[%2];"
                     : "=l"(w01), "=l"(w23) : "r"(wa + (uint32_t)(j * 16)));
                #pragma unroll
                for (int d = 0; d < 2; ++d) {
                    asm ("fma.rn.f32x2 %0,%1,%2,%0;" : "+l"(acc[d][j]) : "l"(fa[d][0]), "l"(w01));
                    asm ("fma.rn.f32x2 %0,%1,%2,%0;" : "+l"(acc[d][j]) : "l"(fa[d][1]), "l"(w23));
                }
            }
        }
    }
    __syncthreads();   // all warps done reading stage buffers before reuse as sRed

    // ---- reduce: collapse f32x2 halves, then across 8 warps via smem ----
    float val[2][8];
    #pragma unroll
    for (int d = 0; d < 2; ++d)
        #pragma unroll
        for (int j = 0; j < 8; ++j) {
            uint32_t lo, hi;
            asm ("mov.b64 {%0,%1},%2;" : "=r"(lo), "=r"(hi) : "l"(acc[d][j]));
            val[d][j] = __uint_as_float(lo) + __uint_as_float(hi);
        }

    float* sRed = reinterpret_cast<float*>(smem);          // [8 warps][32 rows][17] pad
    #pragma unroll
    for (int d = 0; d < 2; ++d)
        #pragma unroll
        for (int j = 0; j < 8; ++j)
            sRed[(s * TILE_ROWS + (rg + 16 * d)) * 17 + (j0 + j)] = val[d][j];
    __syncthreads();

    float* sOut = reinterpret_cast<float*>(smem + 8 * TILE_ROWS * 17 * 4);  // [32][17]
    {
        int o = t;                       // 0..255 covers 0..511 in 2 steps
        #pragma unroll
        for (int i = 0; i < 2; ++i, o += 256) {
            int row = o >> 4, j = o & 15;
            float sum = 0.0f;
            #pragma unroll
            for (int ww = 0; ww < 8; ++ww) sum += sRed[(ww * TILE_ROWS + row) * 17 + j];
            sOut[row * 17 + j] = sum;
        }
    }
    __syncthreads();

    // ---- epilogue: bias + sigmoid + stable top-3 + threshold + stores ----
    if (t < TILE_ROWS) {
        float v[16];
        #pragma unroll
        for (int j = 0; j < 16; ++j) v[j] = sOut[t * 17 + j];

        float bx[12];
        #pragma unroll
        for (int j = 0; j < 12; ++j) bx[j] = v[j] + bb[j];
        float conf[3];
        #pragma unroll
        for (int a = 0; a < 3; ++a)
            conf[a] = 1.0f / (1.0f + expf(-(v[12 + a] + bc[a])));

        // stable descending sort of 3 (matches jax.lax.top_k tie-breaking)
        int i0 = 0, i1 = 1, i2 = 2, tmp;
        if (conf[i0] < conf[i1]) { tmp = i0; i0 = i1; i1 = tmp; }
        if (conf[i1] < conf[i2]) { tmp = i1; i1 = i2; i2 = tmp; }
        if (conf[i0] < conf[i1]) { tmp = i0; i0 = i1; i1 = tmp; }
        int ord[3] = { i0, i1, i2 };

        const int grow = rowBase + t;
        float4* bo = reinterpret_cast<float4*>(out);   // boxes: [row][3][4]
        #pragma unroll
        for (int slot = 0; slot < 3; ++slot) {
            int a = ord[slot];
            float c = conf[a];
            bool vld = c > 0.5f;
            float4 b4 = vld ? make_float4(bx[a * 4 + 0], bx[a * 4 + 1], bx[a * 4 + 2], bx[a * 4 + 3])
                            : make_float4(0.f, 0.f, 0.f, 0.f);
            bo[grow * 3 + slot] = b4;
            if (writeConf)  out[BOXES_ELEMS + grow * 3 + slot] = c;
            if (writeValid) out[BOXES_ELEMS + CONF_ELEMS + grow * 3 + slot] = vld ? 1.0f : 0.0f;
        }
    }
}

extern "C" void kernel_launch(void* const* d_in, const int* in_sizes, int n_in,
                              void* d_out, int out_size) {
    const float* feat = (const float*)d_in[0];   // [32,512,2048] f32
    const float* Wb   = (const float*)d_in[1];   // [2048,12]
    const float* bb   = (const float*)d_in[2];   // [12]
    const float* Wc   = (const float*)d_in[3];   // [2048,3]
    const float* bc   = (const float*)d_in[4];   // [3]
    float* out = (float*)d_out;

    cudaFuncSetAttribute(detector_main, cudaFuncAttributeMaxDynamicSharedMemorySize, SMEM_BYTES);

    prepack_kernel<<<64, 512>>>(Wb, Wc);

    int writeConf  = (out_size >= BOXES_ELEMS + CONF_ELEMS) ? 1 : 0;
    int writeValid = (out_size >= BOXES_ELEMS + 2 * CONF_ELEMS) ? 1 : 0;
    detector_main<<<NCTA, NTHREADS, SMEM_BYTES>>>(feat, bb, bc, out, writeConf, writeValid);
}